// round 12
// baseline (speedup 1.0000x reference)
#include <cuda_runtime.h>
#include <cuda_bf16.h>
#include <cstdint>
#include <math.h>

#define BB 2048
#define TT 200
#define EE 64
#define TC 50

// ---- persistent device scratch (b-invariant precompute) ----
__device__ float              g_ibg[BB];      // item_b[i[c]]
__device__ unsigned long long g_DP[1024];     // (A2-A3) pairs, [j*64+kp]
__device__ unsigned long long g_AP[1024];     // A4(att) pairs, [j*64+kp]
__device__ float              g_S[2048];      // A1+A3          [k*16+j]
__device__ float              g_uhi[128];     // tf32-rounded u = aw4 @ wv[0:128]
__device__ float              g_ulo[128];     // residual u - uhi
__device__ float              g_wvq[128];     // wv[128:256]
__device__ float              g_C[1];         // collapsed constant

__device__ __forceinline__ void ffma2(unsigned long long& d,
                                      unsigned long long a,
                                      unsigned long long b) {
    asm("fma.rn.f32x2 %0, %1, %2, %0;" : "+l"(d) : "l"(a), "l"(b));
}
__device__ __forceinline__ unsigned long long pack2(float lo, float hi) {
    unsigned long long r;
    asm("mov.b64 %0, {%1, %2};" : "=l"(r) : "f"(lo), "f"(hi));
    return r;
}
__device__ __forceinline__ float tf32_rna(float x) {
    float r;
    asm("cvt.rna.tf32.f32 %0, %1;" : "=f"(r) : "f"(x));
    return r;
}
__device__ __forceinline__ uint32_t smem_u32(const void* p) {
    uint32_t a;
    asm("{ .reg .u64 t; cvta.to.shared.u64 t, %1; cvt.u32.u64 %0, t; }"
        : "=r"(a) : "l"(p));
    return a;
}

__device__ __forceinline__ float sigmoid_fast(float x) {
    float e;
    asm("ex2.approx.f32 %0, %1;" : "=f"(e) : "f"(x * -1.4426950408889634f));
    float d = 1.0f + e, r;
    asm("rcp.approx.f32 %0, %1;" : "=f"(r) : "f"(d));
    return r;
}

__device__ __forceinline__ void mma_tf32(float& d0, float& d1, float& d2, float& d3,
                                         unsigned a0, unsigned a1, unsigned a2, unsigned a3,
                                         unsigned b0, unsigned b1) {
    asm volatile(
        "mma.sync.aligned.m16n8k8.row.col.f32.tf32.tf32.f32 "
        "{%0,%1,%2,%3}, {%4,%5,%6,%7}, {%8,%9}, {%0,%1,%2,%3};"
        : "+f"(d0), "+f"(d1), "+f"(d2), "+f"(d3)
        : "r"(a0), "r"(a1), "r"(a2), "r"(a3), "r"(b0), "r"(b1));
}

// ---- K0: b-invariant precompute (incl. full linear-head collapse) ----
__global__ void k0_kernel(const int* __restrict__ iidx, const float* __restrict__ item_b,
                          const float* __restrict__ aw1,
                          const float* __restrict__ aw4, const float* __restrict__ ab4,
                          const float* __restrict__ bn_gamma, const float* __restrict__ bn_beta,
                          const float* __restrict__ bn_mean, const float* __restrict__ bn_var,
                          const float* __restrict__ w1, const float* __restrict__ b1,
                          const float* __restrict__ w2, const float* __restrict__ b2,
                          const float* __restrict__ w3, const float* __restrict__ b3) {
    int blk = blockIdx.x, tid = threadIdx.x;
    if (blk < 8) {
        int c = blk * 256 + tid;
        g_ibg[c] = item_b[iidx[c]];
    } else if (blk == 8) {
        for (int e = tid; e < 1024; e += 256) {
            int j = e >> 6, kp = e & 63;
            int k0 = 2 * kp, k1 = k0 + 1;
            float d0 = aw1[(128 + k0) * 16 + j] - aw1[(256 + k0) * 16 + j];
            float d1 = aw1[(128 + k1) * 16 + j] - aw1[(256 + k1) * 16 + j];
            g_DP[e] = pack2(d0, d1);
            g_AP[e] = pack2(aw1[(384 + k0) * 16 + j], aw1[(384 + k1) * 16 + j]);
        }
    } else if (blk == 9) {
        for (int idx = tid; idx < 2048; idx += 256) {
            int k = idx >> 4, j = idx & 15;
            g_S[idx] = aw1[k * 16 + j] + aw1[(256 + k) * 16 + j];
        }
    } else {
        // linear-head collapse: wv = BNfold(w1)@w2@w3 ; u = aw4@wv[0:128]
        __shared__ float wv[256];
        __shared__ float redC[256];
        int d = tid;
        float v2[16];
        #pragma unroll
        for (int j = 0; j < 16; j++) {
            float a = 0.0f;
            #pragma unroll
            for (int o = 0; o < 8; o++) a = fmaf(w2[j * 8 + o], w3[o], a);
            v2[j] = a;
        }
        float wsum = 0.0f;
        #pragma unroll
        for (int j = 0; j < 16; j++) wsum = fmaf(w1[d * 16 + j], v2[j], wsum);
        float g   = bn_gamma[d] * rsqrtf(bn_var[d] + 1e-3f);
        float wvd = g * wsum;
        wv[d] = wvd;
        float off = bn_beta[d] - bn_mean[d] * g;
        float pc  = off * wsum;
        if (d < 128) pc = fmaf(ab4[d], wvd, pc);
        if (d == 0) {
            float c = b3[0];
            #pragma unroll
            for (int o = 0; o < 8; o++) c = fmaf(b2[o], w3[o], c);
            #pragma unroll
            for (int j = 0; j < 16; j++) c = fmaf(b1[j], v2[j], c);
            pc += c;
        }
        redC[d] = pc;
        __syncthreads();
        if (tid < 128) redC[tid] += redC[tid + 128];
        __syncthreads();
        if (tid < 64) redC[tid] += redC[tid + 64];
        __syncthreads();
        if (tid < 32) {
            float c = redC[tid] + redC[tid + 32];
            #pragma unroll
            for (int o = 16; o; o >>= 1) c += __shfl_xor_sync(0xffffffffu, c, o);
            if (tid == 0) g_C[0] = c;
        }
        if (tid < 128) {
            float a = 0.0f;
            #pragma unroll 4
            for (int dd = 0; dd < 128; dd++) a = fmaf(aw4[tid * 128 + dd], wv[dd], a);
            float hi = tf32_rna(a);
            g_uhi[tid] = hi;
            g_ulo[tid] = a - hi;
        } else {
            g_wvq[tid - 128] = wv[tid];
        }
    }
}

// h FIRST, wt right after: MMA A rows 50..63 overflow into wt
// (read-only, finite, masked via trow<rem — never stored).
struct Smem {
    float h[TC * 128];      // staged h chunk [t][k] (raw f32; MMA truncates to tf32)
    float wt[24 * 128];     // rows 0-15: W_eff[j][k]; 16: u_hi; 17: u_lo; 18-23: 0
    float q[128];
    float cb[16];
    float redf[256];
    float aw2s[128];
    float ab2s[8], aw3s[8], misc[8];
    float redz[8], redw[8], redq[8];
    int   hid[200];
};

__global__ void __launch_bounds__(256, 4) din_main(
    const int* __restrict__ iidx, const int* __restrict__ hist_i,
    const int* __restrict__ sl, const int* __restrict__ category_list,
    const float* __restrict__ item_emb, const float* __restrict__ cat_emb,
    const float* __restrict__ ab1,
    const float* __restrict__ aw2, const float* __restrict__ ab2,
    const float* __restrict__ aw3, const float* __restrict__ ab3,
    float* __restrict__ out)
{
    extern __shared__ char smraw[];
    Smem& s = *reinterpret_cast<Smem*>(smraw);

    const int b    = blockIdx.x;
    const int tid  = threadIdx.x;
    const int warp = tid >> 5, lane = tid & 31;

    const int ib   = iidx[b];
    const int icat = category_list[ib];
    const int slb  = sl[b];

    // ---- phase 0 ----
    if (tid < 128) s.q[tid] = (tid < 64) ? item_emb[(size_t)ib * EE + tid]
                                         : cat_emb[(size_t)icat * EE + (tid - 64)];
    if (tid < 200) s.hid[tid] = hist_i[b * TT + tid];
    if (tid < 128) s.aw2s[tid] = aw2[tid];
    if (tid < 8) { s.ab2s[tid] = ab2[tid]; s.aw3s[tid] = aw3[tid]; }
    if (tid == 0) s.misc[0] = ab3[0];
    __syncthreads();

    // ---- phase 1: W_eff -> wt rows 0-15 (swizzled); rows 16-23: u_hi/u_lo/0; cb ----
    #pragma unroll
    for (int e = tid; e < 1024; e += 256) {
        int j = e >> 6, kp = e & 63;
        unsigned long long qp = *(const unsigned long long*)(s.q + 2 * kp);
        unsigned long long d  = g_DP[e];
        ffma2(d, qp, g_AP[e]);
        int col = (2 * kp) ^ ((j & 7) << 2);
        *(unsigned long long*)(s.wt + j * 128 + col) = d;
    }
    #pragma unroll
    for (int e = tid; e < 1024; e += 256) {
        int row = 16 + (e >> 7), k = e & 127;
        float v = (row == 16) ? g_uhi[k] : (row == 17) ? g_ulo[k] : 0.0f;
        int col = k ^ ((row & 7) << 2);
        s.wt[row * 128 + col] = v;
    }
    {
        int j = tid & 15, ch = tid >> 4;
        float p = 0.0f;
        #pragma unroll
        for (int r = 0; r < 8; r++) {
            int k = ch * 8 + r;
            p = fmaf(s.q[k], g_S[k * 16 + j], p);
        }
        s.redf[ch * 16 + j] = p;
    }
    __syncthreads();
    if (tid < 16) {
        float a = ab1[tid];
        #pragma unroll
        for (int ch = 0; ch < 16; ch++) a += s.redf[ch * 16 + tid];
        s.cb[tid] = a;
    }
    __syncthreads();

    float zacc = 0.0f, wacc = 0.0f;
    const uint32_t hbase = smem_u32(s.h);
    const int li = lane & 15, table = lane >> 4;

    #pragma unroll 1
    for (int c = 0; c < 4; c++) {
        const int tbase = c * TC;
        if (tbase >= slb) break;                 // slb block-uniform -> legal
        const int rem = min(TC, slb - tbase);

        // stage via cp.async.cg 16B: one t-row per warp-iter, half-warp per table.
        // 16B chunks stay contiguous under the (t&7)<<2 float-XOR swizzle.
        for (int tl = warp; tl < rem; tl += 8) {
            int hd = s.hid[tbase + tl];
            const float* src = (table ? cat_emb : item_emb) + (size_t)hd * EE + li * 4;
            uint32_t dst = hbase + (uint32_t)tl * 512u
                         + (uint32_t)(((table * 16 + li) ^ (tl & 7)) * 16);
            asm volatile("cp.async.cg.shared.global [%0], [%1], 16;"
                         :: "r"(dst), "l"(src));
        }
        asm volatile("cp.async.commit_group;");
        asm volatile("cp.async.wait_group 0;" ::: "memory");
        __syncthreads();

        // mma (3 n-tiles: MLP j0-15 + u dot) + in-register sigmoid MLP (warps 0-3)
        if (warp < 4 && warp * 16 < rem) {
            int g = lane >> 2, qd = lane & 3;
            int trowA = warp * 16 + g, trowB = trowA + 8;
            int xsw = g << 2;
            const float* hA0 = s.h + trowA * 128;
            const float* hA1 = s.h + trowB * 128;
            const float* bB0 = s.wt + g * 128;
            const float* bB1 = bB0 + 8 * 128;
            const float* bB2 = bB0 + 16 * 128;
            float d00 = 0.f, d01 = 0.f, d02 = 0.f, d03 = 0.f;
            float d10 = 0.f, d11 = 0.f, d12 = 0.f, d13 = 0.f;
            float e0 = 0.f, e1 = 0.f, e2 = 0.f, e3 = 0.f;
            #pragma unroll
            for (int ks = 0; ks < 16; ks++) {
                int c1 = (8 * ks + qd) ^ xsw;
                int c2 = c1 ^ 4;
                unsigned a0 = __float_as_uint(hA0[c1]);
                unsigned a1 = __float_as_uint(hA1[c1]);
                unsigned a2 = __float_as_uint(hA0[c2]);
                unsigned a3 = __float_as_uint(hA1[c2]);
                unsigned b0 = __float_as_uint(bB0[c1]);
                unsigned b1 = __float_as_uint(bB0[c2]);
                unsigned b2v = __float_as_uint(bB1[c1]);
                unsigned b3v = __float_as_uint(bB1[c2]);
                unsigned b4 = __float_as_uint(bB2[c1]);
                unsigned b5 = __float_as_uint(bB2[c2]);
                mma_tf32(d00, d01, d02, d03, a0, a1, a2, a3, b0, b1);
                mma_tf32(d10, d11, d12, d13, a0, a1, a2, a3, b2v, b3v);
                mma_tf32(e0, e1, e2, e3, a0, a1, a2, a3, b4, b5);
            }
            int j0 = 2 * qd, j1 = j0 + 1, j2 = j0 + 8, j3 = j0 + 9;
            float cb0 = s.cb[j0], cb1 = s.cb[j1], cb2 = s.cb[j2], cb3 = s.cb[j3];
            float xA0 = sigmoid_fast(d00 + cb0), xA1 = sigmoid_fast(d01 + cb1);
            float xA2 = sigmoid_fast(d10 + cb2), xA3 = sigmoid_fast(d11 + cb3);
            float xB0 = sigmoid_fast(d02 + cb0), xB1 = sigmoid_fast(d03 + cb1);
            float xB2 = sigmoid_fast(d12 + cb2), xB3 = sigmoid_fast(d13 + cb3);
            float yA[8], yB[8];
            #pragma unroll
            for (int o = 0; o < 8; o++) {
                float w0 = s.aw2s[j0 * 8 + o], w1v = s.aw2s[j1 * 8 + o];
                float w2v = s.aw2s[j2 * 8 + o], w3v = s.aw2s[j3 * 8 + o];
                yA[o] = fmaf(xA0, w0, fmaf(xA1, w1v, fmaf(xA2, w2v, xA3 * w3v)));
                yB[o] = fmaf(xB0, w0, fmaf(xB1, w1v, fmaf(xB2, w2v, xB3 * w3v)));
            }
            #pragma unroll
            for (int o = 0; o < 8; o++) {
                yA[o] += __shfl_xor_sync(0xffffffffu, yA[o], 1);
                yA[o] += __shfl_xor_sync(0xffffffffu, yA[o], 2);
                yB[o] += __shfl_xor_sync(0xffffffffu, yB[o], 1);
                yB[o] += __shfl_xor_sync(0xffffffffu, yB[o], 2);
            }
            int oa = 2 * qd, ob = oa + 1;
            float a2a = s.ab2s[oa], a2b = s.ab2s[ob];
            float a3a = s.aw3s[oa], a3b = s.aw3s[ob];
            float pA = fmaf(sigmoid_fast(yA[oa] + a2a), a3a,
                            sigmoid_fast(yA[ob] + a2b) * a3b);
            float pB = fmaf(sigmoid_fast(yB[oa] + a2a), a3a,
                            sigmoid_fast(yB[ob] + a2b) * a3b);
            pA += __shfl_xor_sync(0xffffffffu, pA, 1);
            pA += __shfl_xor_sync(0xffffffffu, pA, 2);
            pB += __shfl_xor_sync(0xffffffffu, pB, 1);
            pB += __shfl_xor_sync(0xffffffffu, pB, 2);
            if (qd == 0) {
                float ab3v = s.misc[0];
                if (trowA < rem) {
                    float eA = __expf((pA + ab3v) * 0.08838834764831844f);
                    zacc += eA;
                    wacc = fmaf(eA, e0 + e1, wacc);   // h·u_hi + h·u_lo
                }
                if (trowB < rem) {
                    float eB = __expf((pB + ab3v) * 0.08838834764831844f);
                    zacc += eB;
                    wacc = fmaf(eB, e2 + e3, wacc);
                }
            }
        }
        __syncthreads();   // h consumed; safe to restage
    }

    // ---- epilogue: scalar = wacc/Z + q·wvq + C ----
    float s2p = (tid < 128) ? s.q[tid] * g_wvq[tid] : 0.0f;
    #pragma unroll
    for (int o = 16; o; o >>= 1) {
        zacc += __shfl_xor_sync(0xffffffffu, zacc, o);
        wacc += __shfl_xor_sync(0xffffffffu, wacc, o);
        s2p  += __shfl_xor_sync(0xffffffffu, s2p, o);
    }
    if (lane == 0) { s.redz[warp] = zacc; s.redw[warp] = wacc; s.redq[warp] = s2p; }
    __syncthreads();
    if (tid == 0) {
        float Z = 0.f, W = 0.f, S2 = 0.f;
        #pragma unroll
        for (int w = 0; w < 8; w++) { Z += s.redz[w]; W += s.redw[w]; S2 += s.redq[w]; }
        s.misc[3] = W / Z + S2 + g_C[0];
    }
    __syncthreads();

    // fused output row
    float s3 = s.misc[3];
    const float4* g4 = (const float4*)g_ibg;
    float4* o4 = (float4*)(out + (size_t)b * BB);
    #pragma unroll
    for (int c4 = tid; c4 < BB / 4; c4 += 256) {
        float4 v = g4[c4];
        v.x += s3; v.y += s3; v.z += s3; v.w += s3;
        o4[c4] = v;
    }
}

extern "C" void kernel_launch(void* const* d_in, const int* in_sizes, int n_in,
                              void* d_out, int out_size) {
    const int*   i_arr   = (const int*)d_in[1];
    const int*   hist_i  = (const int*)d_in[2];
    const int*   sl      = (const int*)d_in[3];
    const int*   catlist = (const int*)d_in[4];
    const float* item_emb = (const float*)d_in[5];
    const float* cat_emb  = (const float*)d_in[6];
    const float* item_b   = (const float*)d_in[7];
    const float* aw1 = (const float*)d_in[8];
    const float* ab1 = (const float*)d_in[9];
    const float* aw2 = (const float*)d_in[10];
    const float* ab2 = (const float*)d_in[11];
    const float* aw3 = (const float*)d_in[12];
    const float* ab3 = (const float*)d_in[13];
    const float* aw4 = (const float*)d_in[14];
    const float* ab4 = (const float*)d_in[15];
    const float* bn_gamma = (const float*)d_in[16];
    const float* bn_beta  = (const float*)d_in[17];
    const float* bn_mean  = (const float*)d_in[18];
    const float* bn_var   = (const float*)d_in[19];
    const float* w1 = (const float*)d_in[20];
    const float* b1 = (const float*)d_in[21];
    const float* w2 = (const float*)d_in[22];
    const float* b2 = (const float*)d_in[23];
    const float* w3 = (const float*)d_in[24];
    const float* b3 = (const float*)d_in[25];
    float* out = (float*)d_out;

    static int smem_set = 0;
    if (!smem_set) {
        cudaFuncSetAttribute(din_main, cudaFuncAttributeMaxDynamicSharedMemorySize,
                             (int)sizeof(Smem));
        smem_set = 1;
    }

    k0_kernel<<<11, 256>>>(i_arr, item_b, aw1, aw4, ab4,
                           bn_gamma, bn_beta, bn_mean, bn_var,
                           w1, b1, w2, b2, w3, b3);
    din_main<<<BB, 256, sizeof(Smem)>>>(
        i_arr, hist_i, sl, catlist, item_emb, cat_emb,
        ab1, aw2, ab2, aw3, ab3, out);
}

// round 13
// speedup vs baseline: 1.0037x; 1.0037x over previous
#include <cuda_runtime.h>
#include <cuda_bf16.h>
#include <cstdint>
#include <math.h>

#define BB 2048
#define TT 200
#define EE 64
#define TC 50

// ---- persistent device scratch (b-invariant precompute) ----
__device__ float              g_ibg[BB];      // item_b[i[c]]
__device__ unsigned long long g_DP[1024];     // (A2-A3) pairs, [j*64+kp]
__device__ unsigned long long g_AP[1024];     // A4(att) pairs, [j*64+kp]
__device__ float              g_S[2048];      // A1+A3          [k*16+j]
__device__ float              g_uhi[128];     // tf32-rounded u = aw4 @ wv[0:128]
__device__ float              g_ulo[128];     // residual u - uhi
__device__ float              g_wvq[128];     // wv[128:256]
__device__ float              g_C[1];         // collapsed constant

__device__ __forceinline__ void ffma2(unsigned long long& d,
                                      unsigned long long a,
                                      unsigned long long b) {
    asm("fma.rn.f32x2 %0, %1, %2, %0;" : "+l"(d) : "l"(a), "l"(b));
}
__device__ __forceinline__ unsigned long long pack2(float lo, float hi) {
    unsigned long long r;
    asm("mov.b64 %0, {%1, %2};" : "=l"(r) : "f"(lo), "f"(hi));
    return r;
}
__device__ __forceinline__ float tf32_rna(float x) {
    float r;
    asm("cvt.rna.tf32.f32 %0, %1;" : "=f"(r) : "f"(x));
    return r;
}
__device__ __forceinline__ uint32_t smem_u32(const void* p) {
    uint32_t a;
    asm("{ .reg .u64 t; cvta.to.shared.u64 t, %1; cvt.u32.u64 %0, t; }"
        : "=r"(a) : "l"(p));
    return a;
}

__device__ __forceinline__ float sigmoid_fast(float x) {
    float e;
    asm("ex2.approx.f32 %0, %1;" : "=f"(e) : "f"(x * -1.4426950408889634f));
    float d = 1.0f + e, r;
    asm("rcp.approx.f32 %0, %1;" : "=f"(r) : "f"(d));
    return r;
}

__device__ __forceinline__ void mma_tf32(float& d0, float& d1, float& d2, float& d3,
                                         unsigned a0, unsigned a1, unsigned a2, unsigned a3,
                                         unsigned b0, unsigned b1) {
    asm volatile(
        "mma.sync.aligned.m16n8k8.row.col.f32.tf32.tf32.f32 "
        "{%0,%1,%2,%3}, {%4,%5,%6,%7}, {%8,%9}, {%0,%1,%2,%3};"
        : "+f"(d0), "+f"(d1), "+f"(d2), "+f"(d3)
        : "r"(a0), "r"(a1), "r"(a2), "r"(a3), "r"(b0), "r"(b1));
}

// ---- K0: b-invariant precompute (incl. full linear-head collapse) ----
__global__ void k0_kernel(const int* __restrict__ iidx, const float* __restrict__ item_b,
                          const float* __restrict__ aw1,
                          const float* __restrict__ aw4, const float* __restrict__ ab4,
                          const float* __restrict__ bn_gamma, const float* __restrict__ bn_beta,
                          const float* __restrict__ bn_mean, const float* __restrict__ bn_var,
                          const float* __restrict__ w1, const float* __restrict__ b1,
                          const float* __restrict__ w2, const float* __restrict__ b2,
                          const float* __restrict__ w3, const float* __restrict__ b3) {
    int blk = blockIdx.x, tid = threadIdx.x;
    if (blk < 8) {
        int c = blk * 256 + tid;
        g_ibg[c] = item_b[iidx[c]];
    } else if (blk == 8) {
        for (int e = tid; e < 1024; e += 256) {
            int j = e >> 6, kp = e & 63;
            int k0 = 2 * kp, k1 = k0 + 1;
            float d0 = aw1[(128 + k0) * 16 + j] - aw1[(256 + k0) * 16 + j];
            float d1 = aw1[(128 + k1) * 16 + j] - aw1[(256 + k1) * 16 + j];
            g_DP[e] = pack2(d0, d1);
            g_AP[e] = pack2(aw1[(384 + k0) * 16 + j], aw1[(384 + k1) * 16 + j]);
        }
    } else if (blk == 9) {
        for (int idx = tid; idx < 2048; idx += 256) {
            int k = idx >> 4, j = idx & 15;
            g_S[idx] = aw1[k * 16 + j] + aw1[(256 + k) * 16 + j];
        }
    } else {
        // linear-head collapse: wv = BNfold(w1)@w2@w3 ; u = aw4@wv[0:128]
        __shared__ float wv[256];
        __shared__ float redC[256];
        int d = tid;
        float v2[16];
        #pragma unroll
        for (int j = 0; j < 16; j++) {
            float a = 0.0f;
            #pragma unroll
            for (int o = 0; o < 8; o++) a = fmaf(w2[j * 8 + o], w3[o], a);
            v2[j] = a;
        }
        float wsum = 0.0f;
        #pragma unroll
        for (int j = 0; j < 16; j++) wsum = fmaf(w1[d * 16 + j], v2[j], wsum);
        float g   = bn_gamma[d] * rsqrtf(bn_var[d] + 1e-3f);
        float wvd = g * wsum;
        wv[d] = wvd;
        float off = bn_beta[d] - bn_mean[d] * g;
        float pc  = off * wsum;
        if (d < 128) pc = fmaf(ab4[d], wvd, pc);
        if (d == 0) {
            float c = b3[0];
            #pragma unroll
            for (int o = 0; o < 8; o++) c = fmaf(b2[o], w3[o], c);
            #pragma unroll
            for (int j = 0; j < 16; j++) c = fmaf(b1[j], v2[j], c);
            pc += c;
        }
        redC[d] = pc;
        __syncthreads();
        if (tid < 128) redC[tid] += redC[tid + 128];
        __syncthreads();
        if (tid < 64) redC[tid] += redC[tid + 64];
        __syncthreads();
        if (tid < 32) {
            float c = redC[tid] + redC[tid + 32];
            #pragma unroll
            for (int o = 16; o; o >>= 1) c += __shfl_xor_sync(0xffffffffu, c, o);
            if (tid == 0) g_C[0] = c;
        }
        if (tid < 128) {
            float a = 0.0f;
            #pragma unroll 4
            for (int dd = 0; dd < 128; dd++) a = fmaf(aw4[tid * 128 + dd], wv[dd], a);
            float hi = tf32_rna(a);
            g_uhi[tid] = hi;
            g_ulo[tid] = a - hi;
        } else {
            g_wvq[tid - 128] = wv[tid];
        }
    }
}

// h FIRST, wt right after: MMA A rows 50..63 overflow into wt
// (read-only, finite, masked via trow<rem — never stored).
struct Smem {
    float h[TC * 128];      // staged h chunk [t][k] (raw f32; MMA truncates to tf32)
    float wt[24 * 128];     // rows 0-15: W_eff[j][k]; 16: u_hi; 17: u_lo; 18-23: 0
    float q[128];
    float cb[16];
    float redf[256];
    float aw2s[128];
    float ab2s[8], aw3s[8], misc[8];
    float redz[8], redw[8], redq[8];
    int   hid[200];
};

__global__ void __launch_bounds__(256, 4) din_main(
    const int* __restrict__ iidx, const int* __restrict__ hist_i,
    const int* __restrict__ sl, const int* __restrict__ category_list,
    const float* __restrict__ item_emb, const float* __restrict__ cat_emb,
    const float* __restrict__ ab1,
    const float* __restrict__ aw2, const float* __restrict__ ab2,
    const float* __restrict__ aw3, const float* __restrict__ ab3,
    float* __restrict__ out)
{
    extern __shared__ char smraw[];
    Smem& s = *reinterpret_cast<Smem*>(smraw);

    const int b    = blockIdx.x;
    const int tid  = threadIdx.x;
    const int warp = tid >> 5, lane = tid & 31;

    const int ib   = iidx[b];
    const int icat = category_list[ib];
    const int slb  = sl[b];

    // ---- phase 0 ----
    if (tid < 128) s.q[tid] = (tid < 64) ? item_emb[(size_t)ib * EE + tid]
                                         : cat_emb[(size_t)icat * EE + (tid - 64)];
    if (tid < 200) s.hid[tid] = hist_i[b * TT + tid];
    if (tid < 128) s.aw2s[tid] = aw2[tid];
    if (tid < 8) { s.ab2s[tid] = ab2[tid]; s.aw3s[tid] = aw3[tid]; }
    if (tid == 0) s.misc[0] = ab3[0];
    __syncthreads();

    // ---- phase 1: W_eff -> wt rows 0-15 (swizzled); rows 16-23: u_hi/u_lo/0; cb ----
    #pragma unroll
    for (int e = tid; e < 1024; e += 256) {
        int j = e >> 6, kp = e & 63;
        unsigned long long qp = *(const unsigned long long*)(s.q + 2 * kp);
        unsigned long long d  = g_DP[e];
        ffma2(d, qp, g_AP[e]);
        int col = (2 * kp) ^ ((j & 7) << 2);
        *(unsigned long long*)(s.wt + j * 128 + col) = d;
    }
    #pragma unroll
    for (int e = tid; e < 1024; e += 256) {
        int row = 16 + (e >> 7), k = e & 127;
        float v = (row == 16) ? g_uhi[k] : (row == 17) ? g_ulo[k] : 0.0f;
        int col = k ^ ((row & 7) << 2);
        s.wt[row * 128 + col] = v;
    }
    {
        int j = tid & 15, ch = tid >> 4;
        float p = 0.0f;
        #pragma unroll
        for (int r = 0; r < 8; r++) {
            int k = ch * 8 + r;
            p = fmaf(s.q[k], g_S[k * 16 + j], p);
        }
        s.redf[ch * 16 + j] = p;
    }
    __syncthreads();
    if (tid < 16) {
        float a = ab1[tid];
        #pragma unroll
        for (int ch = 0; ch < 16; ch++) a += s.redf[ch * 16 + tid];
        s.cb[tid] = a;
    }
    __syncthreads();

    float zacc = 0.0f, wacc = 0.0f;
    const uint32_t hbase = smem_u32(s.h);
    const int li = lane & 15, table = lane >> 4;

    #pragma unroll 1
    for (int c = 0; c < 4; c++) {
        const int tbase = c * TC;
        if (tbase >= slb) break;                 // slb block-uniform -> legal
        const int rem = min(TC, slb - tbase);

        // stage via cp.async.cg 16B: one t-row per warp-iter, half-warp per table.
        // 16B chunks stay contiguous under the (t&7)<<2 float-XOR swizzle.
        for (int tl = warp; tl < rem; tl += 8) {
            int hd = s.hid[tbase + tl];
            const float* src = (table ? cat_emb : item_emb) + (size_t)hd * EE + li * 4;
            uint32_t dst = hbase + (uint32_t)tl * 512u
                         + (uint32_t)(((table * 16 + li) ^ (tl & 7)) * 16);
            asm volatile("cp.async.cg.shared.global [%0], [%1], 16;"
                         :: "r"(dst), "l"(src));
        }
        asm volatile("cp.async.commit_group;");
        asm volatile("cp.async.wait_group 0;" ::: "memory");
        __syncthreads();

        // mma (3 n-tiles: MLP j0-15 + u dot) + in-register sigmoid MLP (warps 0-3)
        if (warp < 4 && warp * 16 < rem) {
            int g = lane >> 2, qd = lane & 3;
            int trowA = warp * 16 + g, trowB = trowA + 8;
            int xsw = g << 2;
            const float* hA0 = s.h + trowA * 128;
            const float* hA1 = s.h + trowB * 128;
            const float* bB0 = s.wt + g * 128;
            const float* bB1 = bB0 + 8 * 128;
            const float* bB2 = bB0 + 16 * 128;
            float d00 = 0.f, d01 = 0.f, d02 = 0.f, d03 = 0.f;
            float d10 = 0.f, d11 = 0.f, d12 = 0.f, d13 = 0.f;
            float e0 = 0.f, e1 = 0.f, e2 = 0.f, e3 = 0.f;
            #pragma unroll
            for (int ks = 0; ks < 16; ks++) {
                int c1 = (8 * ks + qd) ^ xsw;
                int c2 = c1 ^ 4;
                unsigned a0 = __float_as_uint(hA0[c1]);
                unsigned a1 = __float_as_uint(hA1[c1]);
                unsigned a2 = __float_as_uint(hA0[c2]);
                unsigned a3 = __float_as_uint(hA1[c2]);
                unsigned b0 = __float_as_uint(bB0[c1]);
                unsigned b1 = __float_as_uint(bB0[c2]);
                unsigned b2v = __float_as_uint(bB1[c1]);
                unsigned b3v = __float_as_uint(bB1[c2]);
                unsigned b4 = __float_as_uint(bB2[c1]);
                unsigned b5 = __float_as_uint(bB2[c2]);
                mma_tf32(d00, d01, d02, d03, a0, a1, a2, a3, b0, b1);
                mma_tf32(d10, d11, d12, d13, a0, a1, a2, a3, b2v, b3v);
                mma_tf32(e0, e1, e2, e3, a0, a1, a2, a3, b4, b5);
            }
            int j0 = 2 * qd, j1 = j0 + 1, j2 = j0 + 8, j3 = j0 + 9;
            float cb0 = s.cb[j0], cb1 = s.cb[j1], cb2 = s.cb[j2], cb3 = s.cb[j3];
            float xA0 = sigmoid_fast(d00 + cb0), xA1 = sigmoid_fast(d01 + cb1);
            float xA2 = sigmoid_fast(d10 + cb2), xA3 = sigmoid_fast(d11 + cb3);
            float xB0 = sigmoid_fast(d02 + cb0), xB1 = sigmoid_fast(d03 + cb1);
            float xB2 = sigmoid_fast(d12 + cb2), xB3 = sigmoid_fast(d13 + cb3);
            float yA[8], yB[8];
            #pragma unroll
            for (int o = 0; o < 8; o++) {
                float w0 = s.aw2s[j0 * 8 + o], w1v = s.aw2s[j1 * 8 + o];
                float w2v = s.aw2s[j2 * 8 + o], w3v = s.aw2s[j3 * 8 + o];
                yA[o] = fmaf(xA0, w0, fmaf(xA1, w1v, fmaf(xA2, w2v, xA3 * w3v)));
                yB[o] = fmaf(xB0, w0, fmaf(xB1, w1v, fmaf(xB2, w2v, xB3 * w3v)));
            }
            #pragma unroll
            for (int o = 0; o < 8; o++) {
                yA[o] += __shfl_xor_sync(0xffffffffu, yA[o], 1);
                yA[o] += __shfl_xor_sync(0xffffffffu, yA[o], 2);
                yB[o] += __shfl_xor_sync(0xffffffffu, yB[o], 1);
                yB[o] += __shfl_xor_sync(0xffffffffu, yB[o], 2);
            }
            int oa = 2 * qd, ob = oa + 1;
            float a2a = s.ab2s[oa], a2b = s.ab2s[ob];
            float a3a = s.aw3s[oa], a3b = s.aw3s[ob];
            float pA = fmaf(sigmoid_fast(yA[oa] + a2a), a3a,
                            sigmoid_fast(yA[ob] + a2b) * a3b);
            float pB = fmaf(sigmoid_fast(yB[oa] + a2a), a3a,
                            sigmoid_fast(yB[ob] + a2b) * a3b);
            pA += __shfl_xor_sync(0xffffffffu, pA, 1);
            pA += __shfl_xor_sync(0xffffffffu, pA, 2);
            pB += __shfl_xor_sync(0xffffffffu, pB, 1);
            pB += __shfl_xor_sync(0xffffffffu, pB, 2);
            if (qd == 0) {
                float ab3v = s.misc[0];
                if (trowA < rem) {
                    float eA = __expf((pA + ab3v) * 0.08838834764831844f);
                    zacc += eA;
                    wacc = fmaf(eA, e0 + e1, wacc);   // h·u_hi + h·u_lo
                }
                if (trowB < rem) {
                    float eB = __expf((pB + ab3v) * 0.08838834764831844f);
                    zacc += eB;
                    wacc = fmaf(eB, e2 + e3, wacc);
                }
            }
        }
        __syncthreads();   // h consumed; safe to restage
    }

    // ---- epilogue: scalar = wacc/Z + q·wvq + C ----
    float s2p = (tid < 128) ? s.q[tid] * g_wvq[tid] : 0.0f;
    #pragma unroll
    for (int o = 16; o; o >>= 1) {
        zacc += __shfl_xor_sync(0xffffffffu, zacc, o);
        wacc += __shfl_xor_sync(0xffffffffu, wacc, o);
        s2p  += __shfl_xor_sync(0xffffffffu, s2p, o);
    }
    if (lane == 0) { s.redz[warp] = zacc; s.redw[warp] = wacc; s.redq[warp] = s2p; }
    __syncthreads();
    if (tid == 0) {
        float Z = 0.f, W = 0.f, S2 = 0.f;
        #pragma unroll
        for (int w = 0; w < 8; w++) { Z += s.redz[w]; W += s.redw[w]; S2 += s.redq[w]; }
        s.misc[3] = W / Z + S2 + g_C[0];
    }
    __syncthreads();

    // fused output row
    float s3 = s.misc[3];
    const float4* g4 = (const float4*)g_ibg;
    float4* o4 = (float4*)(out + (size_t)b * BB);
    #pragma unroll
    for (int c4 = tid; c4 < BB / 4; c4 += 256) {
        float4 v = g4[c4];
        v.x += s3; v.y += s3; v.z += s3; v.w += s3;
        o4[c4] = v;
    }
}

extern "C" void kernel_launch(void* const* d_in, const int* in_sizes, int n_in,
                              void* d_out, int out_size) {
    const int*   i_arr   = (const int*)d_in[1];
    const int*   hist_i  = (const int*)d_in[2];
    const int*   sl      = (const int*)d_in[3];
    const int*   catlist = (const int*)d_in[4];
    const float* item_emb = (const float*)d_in[5];
    const float* cat_emb  = (const float*)d_in[6];
    const float* item_b   = (const float*)d_in[7];
    const float* aw1 = (const float*)d_in[8];
    const float* ab1 = (const float*)d_in[9];
    const float* aw2 = (const float*)d_in[10];
    const float* ab2 = (const float*)d_in[11];
    const float* aw3 = (const float*)d_in[12];
    const float* ab3 = (const float*)d_in[13];
    const float* aw4 = (const float*)d_in[14];
    const float* ab4 = (const float*)d_in[15];
    const float* bn_gamma = (const float*)d_in[16];
    const float* bn_beta  = (const float*)d_in[17];
    const float* bn_mean  = (const float*)d_in[18];
    const float* bn_var   = (const float*)d_in[19];
    const float* w1 = (const float*)d_in[20];
    const float* b1 = (const float*)d_in[21];
    const float* w2 = (const float*)d_in[22];
    const float* b2 = (const float*)d_in[23];
    const float* w3 = (const float*)d_in[24];
    const float* b3 = (const float*)d_in[25];
    float* out = (float*)d_out;

    static int smem_set = 0;
    if (!smem_set) {
        cudaFuncSetAttribute(din_main, cudaFuncAttributeMaxDynamicSharedMemorySize,
                             (int)sizeof(Smem));
        smem_set = 1;
    }

    k0_kernel<<<11, 256>>>(i_arr, item_b, aw1, aw4, ab4,
                           bn_gamma, bn_beta, bn_mean, bn_var,
                           w1, b1, w2, b2, w3, b3);
    din_main<<<BB, 256, sizeof(Smem)>>>(
        i_arr, hist_i, sl, catlist, item_emb, cat_emb,
        ab1, aw2, ab2, aw3, ab3, out);
}

// round 14
// speedup vs baseline: 1.0393x; 1.0354x over previous
#include <cuda_runtime.h>
#include <cuda_bf16.h>
#include <cstdint>
#include <math.h>

#define BB 2048
#define TT 200
#define EE 64
#define TC 50

// ---- persistent device scratch (b-invariant precompute) ----
__device__ float              g_ibg[BB];      // item_b[i[c]]
__device__ unsigned long long g_DP[1024];     // (A2-A3) pairs, [j*64+kp]
__device__ unsigned long long g_AP[1024];     // A4(att) pairs, [j*64+kp]
__device__ float              g_S[2048];      // A1+A3          [k*16+j]
__device__ float              g_uhi[128];     // tf32-rounded u = aw4 @ wv[0:128]
__device__ float              g_ulo[128];     // residual u - uhi
__device__ float              g_wvq[128];     // wv[128:256]
__device__ float              g_C[1];         // collapsed constant

__device__ __forceinline__ void ffma2(unsigned long long& d,
                                      unsigned long long a,
                                      unsigned long long b) {
    asm("fma.rn.f32x2 %0, %1, %2, %0;" : "+l"(d) : "l"(a), "l"(b));
}
__device__ __forceinline__ unsigned long long pack2(float lo, float hi) {
    unsigned long long r;
    asm("mov.b64 %0, {%1, %2};" : "=l"(r) : "f"(lo), "f"(hi));
    return r;
}
__device__ __forceinline__ float tf32_rna(float x) {
    float r;
    asm("cvt.rna.tf32.f32 %0, %1;" : "=f"(r) : "f"(x));
    return r;
}
__device__ __forceinline__ uint32_t smem_u32(const void* p) {
    uint32_t a;
    asm("{ .reg .u64 t; cvta.to.shared.u64 t, %1; cvt.u32.u64 %0, t; }"
        : "=r"(a) : "l"(p));
    return a;
}

__device__ __forceinline__ float sigmoid_fast(float x) {
    float e;
    asm("ex2.approx.f32 %0, %1;" : "=f"(e) : "f"(x * -1.4426950408889634f));
    float d = 1.0f + e, r;
    asm("rcp.approx.f32 %0, %1;" : "=f"(r) : "f"(d));
    return r;
}

__device__ __forceinline__ void mma_tf32(float& d0, float& d1, float& d2, float& d3,
                                         unsigned a0, unsigned a1, unsigned a2, unsigned a3,
                                         unsigned b0, unsigned b1) {
    asm volatile(
        "mma.sync.aligned.m16n8k8.row.col.f32.tf32.tf32.f32 "
        "{%0,%1,%2,%3}, {%4,%5,%6,%7}, {%8,%9}, {%0,%1,%2,%3};"
        : "+f"(d0), "+f"(d1), "+f"(d2), "+f"(d3)
        : "r"(a0), "r"(a1), "r"(a2), "r"(a3), "r"(b0), "r"(b1));
}

// ---- K0: b-invariant precompute (incl. full linear-head collapse) ----
__global__ void k0_kernel(const int* __restrict__ iidx, const float* __restrict__ item_b,
                          const float* __restrict__ aw1,
                          const float* __restrict__ aw4, const float* __restrict__ ab4,
                          const float* __restrict__ bn_gamma, const float* __restrict__ bn_beta,
                          const float* __restrict__ bn_mean, const float* __restrict__ bn_var,
                          const float* __restrict__ w1, const float* __restrict__ b1,
                          const float* __restrict__ w2, const float* __restrict__ b2,
                          const float* __restrict__ w3, const float* __restrict__ b3) {
    int blk = blockIdx.x, tid = threadIdx.x;
    if (blk < 8) {
        int c = blk * 256 + tid;
        g_ibg[c] = item_b[iidx[c]];
    } else if (blk == 8) {
        for (int e = tid; e < 1024; e += 256) {
            int j = e >> 6, kp = e & 63;
            int k0 = 2 * kp, k1 = k0 + 1;
            float d0 = aw1[(128 + k0) * 16 + j] - aw1[(256 + k0) * 16 + j];
            float d1 = aw1[(128 + k1) * 16 + j] - aw1[(256 + k1) * 16 + j];
            g_DP[e] = pack2(d0, d1);
            g_AP[e] = pack2(aw1[(384 + k0) * 16 + j], aw1[(384 + k1) * 16 + j]);
        }
    } else if (blk == 9) {
        for (int idx = tid; idx < 2048; idx += 256) {
            int k = idx >> 4, j = idx & 15;
            g_S[idx] = aw1[k * 16 + j] + aw1[(256 + k) * 16 + j];
        }
    } else {
        // linear-head collapse: wv = BNfold(w1)@w2@w3 ; u = aw4@wv[0:128]
        __shared__ float wv[256];
        __shared__ float redC[256];
        int d = tid;
        float v2[16];
        #pragma unroll
        for (int j = 0; j < 16; j++) {
            float a = 0.0f;
            #pragma unroll
            for (int o = 0; o < 8; o++) a = fmaf(w2[j * 8 + o], w3[o], a);
            v2[j] = a;
        }
        float wsum = 0.0f;
        #pragma unroll
        for (int j = 0; j < 16; j++) wsum = fmaf(w1[d * 16 + j], v2[j], wsum);
        float g   = bn_gamma[d] * rsqrtf(bn_var[d] + 1e-3f);
        float wvd = g * wsum;
        wv[d] = wvd;
        float off = bn_beta[d] - bn_mean[d] * g;
        float pc  = off * wsum;
        if (d < 128) pc = fmaf(ab4[d], wvd, pc);
        if (d == 0) {
            float c = b3[0];
            #pragma unroll
            for (int o = 0; o < 8; o++) c = fmaf(b2[o], w3[o], c);
            #pragma unroll
            for (int j = 0; j < 16; j++) c = fmaf(b1[j], v2[j], c);
            pc += c;
        }
        redC[d] = pc;
        __syncthreads();
        if (tid < 128) redC[tid] += redC[tid + 128];
        __syncthreads();
        if (tid < 64) redC[tid] += redC[tid + 64];
        __syncthreads();
        if (tid < 32) {
            float c = redC[tid] + redC[tid + 32];
            #pragma unroll
            for (int o = 16; o; o >>= 1) c += __shfl_xor_sync(0xffffffffu, c, o);
            if (tid == 0) g_C[0] = c;
        }
        if (tid < 128) {
            float a = 0.0f;
            #pragma unroll 4
            for (int dd = 0; dd < 128; dd++) a = fmaf(aw4[tid * 128 + dd], wv[dd], a);
            float hi = tf32_rna(a);
            g_uhi[tid] = hi;
            g_ulo[tid] = a - hi;
        } else {
            g_wvq[tid - 128] = wv[tid];
        }
    }
}

// h FIRST, wt right after: MMA A rows 50..63 overflow into wt
// (read-only, finite, masked via trow<rem — never stored).
// Swizzle: col ^= (row&7)<<3 — float2-vectorizable, conflict-free fragments.
// Logical MMA k relabel: logical {qd, qd+4} <-> physical {2qd, 2qd+1}
// (same permutation on A and B => identical contraction).
struct Smem {
    float h[TC * 128];      // staged h chunk [t][k] (raw f32; MMA truncates to tf32)
    float wt[24 * 128];     // rows 0-15: W_eff[j][k]; 16: u_hi; 17: u_lo; 18-23: 0
    float q[128];
    float cb[16];
    float redf[256];
    float aw2s[128];
    float ab2s[8], aw3s[8], misc[8];
    float redz[8], redw[8], redq[8];
    int   hid[200];
};

__global__ void __launch_bounds__(256, 4) din_main(
    const int* __restrict__ iidx, const int* __restrict__ hist_i,
    const int* __restrict__ sl, const int* __restrict__ category_list,
    const float* __restrict__ item_emb, const float* __restrict__ cat_emb,
    const float* __restrict__ ab1,
    const float* __restrict__ aw2, const float* __restrict__ ab2,
    const float* __restrict__ aw3, const float* __restrict__ ab3,
    float* __restrict__ out)
{
    extern __shared__ char smraw[];
    Smem& s = *reinterpret_cast<Smem*>(smraw);

    const int b    = blockIdx.x;
    const int tid  = threadIdx.x;
    const int warp = tid >> 5, lane = tid & 31;

    const int ib   = iidx[b];
    const int icat = category_list[ib];
    const int slb  = sl[b];

    // ---- phase 0 ----
    if (tid < 128) s.q[tid] = (tid < 64) ? item_emb[(size_t)ib * EE + tid]
                                         : cat_emb[(size_t)icat * EE + (tid - 64)];
    if (tid < 200) s.hid[tid] = hist_i[b * TT + tid];
    if (tid < 128) s.aw2s[tid] = aw2[tid];
    if (tid < 8) { s.ab2s[tid] = ab2[tid]; s.aw3s[tid] = aw3[tid]; }
    if (tid == 0) s.misc[0] = ab3[0];
    __syncthreads();

    const uint32_t hbase = smem_u32(s.h);
    const int li = lane & 15, table = lane >> 4;

    // ---- issue chunk-0 staging NOW; overlaps with phase-1 compute ----
    {
        const int rem0 = min(TC, slb);
        for (int tl = warp; tl < rem0; tl += 8) {
            int hd = s.hid[tl];
            const float* src = (table ? cat_emb : item_emb) + (size_t)hd * EE + li * 4;
            uint32_t dst = hbase + (uint32_t)tl * 512u
                         + (uint32_t)((table * 256 + li * 16) ^ ((tl & 7) * 32));
            asm volatile("cp.async.cg.shared.global [%0], [%1], 16;"
                         :: "r"(dst), "l"(src));
        }
        asm volatile("cp.async.commit_group;");
    }

    // ---- phase 1: W_eff -> wt rows 0-15 (swizzled <<3); rows 16-23; cb ----
    #pragma unroll
    for (int e = tid; e < 1024; e += 256) {
        int j = e >> 6, kp = e & 63;
        unsigned long long qp = *(const unsigned long long*)(s.q + 2 * kp);
        unsigned long long d  = g_DP[e];
        ffma2(d, qp, g_AP[e]);
        int col = (2 * kp) ^ ((j & 7) << 3);
        *(unsigned long long*)(s.wt + j * 128 + col) = d;
    }
    #pragma unroll
    for (int e = tid; e < 1024; e += 256) {
        int row = 16 + (e >> 7), k = e & 127;
        float v = (row == 16) ? g_uhi[k] : (row == 17) ? g_ulo[k] : 0.0f;
        int col = k ^ ((row & 7) << 3);
        s.wt[row * 128 + col] = v;
    }
    {
        int j = tid & 15, ch = tid >> 4;
        float p = 0.0f;
        #pragma unroll
        for (int r = 0; r < 8; r++) {
            int k = ch * 8 + r;
            p = fmaf(s.q[k], g_S[k * 16 + j], p);
        }
        s.redf[ch * 16 + j] = p;
    }
    __syncthreads();
    if (tid < 16) {
        float a = ab1[tid];
        #pragma unroll
        for (int ch = 0; ch < 16; ch++) a += s.redf[ch * 16 + tid];
        s.cb[tid] = a;
    }

    float zacc = 0.0f, wacc = 0.0f;

    #pragma unroll 1
    for (int c = 0; c < 4; c++) {
        const int tbase = c * TC;
        if (tbase >= slb) break;                 // slb block-uniform -> legal
        const int rem = min(TC, slb - tbase);

        // chunk c staging already issued (prologue or previous iteration)
        asm volatile("cp.async.wait_group 0;" ::: "memory");
        __syncthreads();

        // mma (3 n-tiles: MLP j0-15 + u dot) + in-register sigmoid MLP (warps 0-3)
        if (warp < 4 && warp * 16 < rem) {
            int g = lane >> 2, qd = lane & 3;
            int trowA = warp * 16 + g, trowB = trowA + 8;
            int xsw = g << 3;
            const float* hA0 = s.h + trowA * 128;
            const float* hA1 = s.h + trowB * 128;
            const float* bB0 = s.wt + g * 128;
            const float* bB1 = bB0 + 8 * 128;
            const float* bB2 = bB0 + 16 * 128;
            float d00 = 0.f, d01 = 0.f, d02 = 0.f, d03 = 0.f;
            float d10 = 0.f, d11 = 0.f, d12 = 0.f, d13 = 0.f;
            float e0 = 0.f, e1 = 0.f, e2 = 0.f, e3 = 0.f;
            #pragma unroll
            for (int ks = 0; ks < 16; ks++) {
                int ca = (8 * ks + 2 * qd) ^ xsw;       // physical float2 base
                float2 aA  = *(const float2*)(hA0 + ca);
                float2 aB  = *(const float2*)(hA1 + ca);
                float2 b0v = *(const float2*)(bB0 + ca);
                float2 b1v = *(const float2*)(bB1 + ca);
                float2 b2v = *(const float2*)(bB2 + ca);
                // logical k=qd -> .x ; logical k=qd+4 -> .y (same relabel A & B)
                mma_tf32(d00, d01, d02, d03,
                         __float_as_uint(aA.x), __float_as_uint(aB.x),
                         __float_as_uint(aA.y), __float_as_uint(aB.y),
                         __float_as_uint(b0v.x), __float_as_uint(b0v.y));
                mma_tf32(d10, d11, d12, d13,
                         __float_as_uint(aA.x), __float_as_uint(aB.x),
                         __float_as_uint(aA.y), __float_as_uint(aB.y),
                         __float_as_uint(b1v.x), __float_as_uint(b1v.y));
                mma_tf32(e0, e1, e2, e3,
                         __float_as_uint(aA.x), __float_as_uint(aB.x),
                         __float_as_uint(aA.y), __float_as_uint(aB.y),
                         __float_as_uint(b2v.x), __float_as_uint(b2v.y));
            }
            int j0 = 2 * qd, j1 = j0 + 1, j2 = j0 + 8, j3 = j0 + 9;
            float cb0 = s.cb[j0], cb1 = s.cb[j1], cb2 = s.cb[j2], cb3 = s.cb[j3];
            float xA0 = sigmoid_fast(d00 + cb0), xA1 = sigmoid_fast(d01 + cb1);
            float xA2 = sigmoid_fast(d10 + cb2), xA3 = sigmoid_fast(d11 + cb3);
            float xB0 = sigmoid_fast(d02 + cb0), xB1 = sigmoid_fast(d03 + cb1);
            float xB2 = sigmoid_fast(d12 + cb2), xB3 = sigmoid_fast(d13 + cb3);
            float yA[8], yB[8];
            #pragma unroll
            for (int o = 0; o < 8; o++) {
                float w0 = s.aw2s[j0 * 8 + o], w1v = s.aw2s[j1 * 8 + o];
                float w2v = s.aw2s[j2 * 8 + o], w3v = s.aw2s[j3 * 8 + o];
                yA[o] = fmaf(xA0, w0, fmaf(xA1, w1v, fmaf(xA2, w2v, xA3 * w3v)));
                yB[o] = fmaf(xB0, w0, fmaf(xB1, w1v, fmaf(xB2, w2v, xB3 * w3v)));
            }
            #pragma unroll
            for (int o = 0; o < 8; o++) {
                yA[o] += __shfl_xor_sync(0xffffffffu, yA[o], 1);
                yA[o] += __shfl_xor_sync(0xffffffffu, yA[o], 2);
                yB[o] += __shfl_xor_sync(0xffffffffu, yB[o], 1);
                yB[o] += __shfl_xor_sync(0xffffffffu, yB[o], 2);
            }
            int oa = 2 * qd, ob = oa + 1;
            float a2a = s.ab2s[oa], a2b = s.ab2s[ob];
            float a3a = s.aw3s[oa], a3b = s.aw3s[ob];
            float pA = fmaf(sigmoid_fast(yA[oa] + a2a), a3a,
                            sigmoid_fast(yA[ob] + a2b) * a3b);
            float pB = fmaf(sigmoid_fast(yB[oa] + a2a), a3a,
                            sigmoid_fast(yB[ob] + a2b) * a3b);
            pA += __shfl_xor_sync(0xffffffffu, pA, 1);
            pA += __shfl_xor_sync(0xffffffffu, pA, 2);
            pB += __shfl_xor_sync(0xffffffffu, pB, 1);
            pB += __shfl_xor_sync(0xffffffffu, pB, 2);
            if (qd == 0) {
                float ab3v = s.misc[0];
                if (trowA < rem) {
                    float eA = __expf((pA + ab3v) * 0.08838834764831844f);
                    zacc += eA;
                    wacc = fmaf(eA, e0 + e1, wacc);   // h·u_hi + h·u_lo
                }
                if (trowB < rem) {
                    float eB = __expf((pB + ab3v) * 0.08838834764831844f);
                    zacc += eB;
                    wacc = fmaf(eB, e2 + e3, wacc);
                }
            }
        }
        __syncthreads();   // h consumed; safe to restage

        // issue staging for next chunk
        const int tb2 = tbase + TC;
        if (tb2 < slb) {
            const int rem2 = min(TC, slb - tb2);
            for (int tl = warp; tl < rem2; tl += 8) {
                int hd = s.hid[tb2 + tl];
                const float* src = (table ? cat_emb : item_emb) + (size_t)hd * EE + li * 4;
                uint32_t dst = hbase + (uint32_t)tl * 512u
                             + (uint32_t)((table * 256 + li * 16) ^ ((tl & 7) * 32));
                asm volatile("cp.async.cg.shared.global [%0], [%1], 16;"
                             :: "r"(dst), "l"(src));
            }
            asm volatile("cp.async.commit_group;");
        }
    }

    // ---- epilogue: scalar = wacc/Z + q·wvq + C ----
    float s2p = (tid < 128) ? s.q[tid] * g_wvq[tid] : 0.0f;
    #pragma unroll
    for (int o = 16; o; o >>= 1) {
        zacc += __shfl_xor_sync(0xffffffffu, zacc, o);
        wacc += __shfl_xor_sync(0xffffffffu, wacc, o);
        s2p  += __shfl_xor_sync(0xffffffffu, s2p, o);
    }
    if (lane == 0) { s.redz[warp] = zacc; s.redw[warp] = wacc; s.redq[warp] = s2p; }
    __syncthreads();
    if (tid == 0) {
        float Z = 0.f, W = 0.f, S2 = 0.f;
        #pragma unroll
        for (int w = 0; w < 8; w++) { Z += s.redz[w]; W += s.redw[w]; S2 += s.redq[w]; }
        s.misc[3] = W / Z + S2 + g_C[0];
    }
    __syncthreads();

    // fused output row
    float s3 = s.misc[3];
    const float4* g4 = (const float4*)g_ibg;
    float4* o4 = (float4*)(out + (size_t)b * BB);
    #pragma unroll
    for (int c4 = tid; c4 < BB / 4; c4 += 256) {
        float4 v = g4[c4];
        v.x += s3; v.y += s3; v.z += s3; v.w += s3;
        o4[c4] = v;
    }
}

extern "C" void kernel_launch(void* const* d_in, const int* in_sizes, int n_in,
                              void* d_out, int out_size) {
    const int*   i_arr   = (const int*)d_in[1];
    const int*   hist_i  = (const int*)d_in[2];
    const int*   sl      = (const int*)d_in[3];
    const int*   catlist = (const int*)d_in[4];
    const float* item_emb = (const float*)d_in[5];
    const float* cat_emb  = (const float*)d_in[6];
    const float* item_b   = (const float*)d_in[7];
    const float* aw1 = (const float*)d_in[8];
    const float* ab1 = (const float*)d_in[9];
    const float* aw2 = (const float*)d_in[10];
    const float* ab2 = (const float*)d_in[11];
    const float* aw3 = (const float*)d_in[12];
    const float* ab3 = (const float*)d_in[13];
    const float* aw4 = (const float*)d_in[14];
    const float* ab4 = (const float*)d_in[15];
    const float* bn_gamma = (const float*)d_in[16];
    const float* bn_beta  = (const float*)d_in[17];
    const float* bn_mean  = (const float*)d_in[18];
    const float* bn_var   = (const float*)d_in[19];
    const float* w1 = (const float*)d_in[20];
    const float* b1 = (const float*)d_in[21];
    const float* w2 = (const float*)d_in[22];
    const float* b2 = (const float*)d_in[23];
    const float* w3 = (const float*)d_in[24];
    const float* b3 = (const float*)d_in[25];
    float* out = (float*)d_out;

    static int smem_set = 0;
    if (!smem_set) {
        cudaFuncSetAttribute(din_main, cudaFuncAttributeMaxDynamicSharedMemorySize,
                             (int)sizeof(Smem));
        smem_set = 1;
    }

    k0_kernel<<<11, 256>>>(i_arr, item_b, aw1, aw4, ab4,
                           bn_gamma, bn_beta, bn_mean, bn_var,
                           w1, b1, w2, b2, w3, b3);
    din_main<<<BB, 256, sizeof(Smem)>>>(
        i_arr, hist_i, sl, catlist, item_emb, cat_emb,
        ab1, aw2, ab2, aw3, ab3, out);
}